// round 3
// baseline (speedup 1.0000x reference)
#include <cuda_runtime.h>
#include <math.h>

// Problem constants
#define NN   128
#define TT   32
#define VV   25
#define CC   256
#define ICC  64
#define SS   3
#define NTV  (NN*TT*VV)        // 102400 rows
#define QKN  (2*SS*ICC)        // 384
#define CATN (SS*CC)           // 768
#define LN_EPS 1e-5f

// ---------------------------------------------------------------------------
// Scratch (device globals; allocations are forbidden). ~630 MB total.
// g_big [NTV,CATN] holds, at different times:
//   - qk  [NTV,QKN]  (start of buffer)   : consumed before cat is written
//   - cat [NTV,CATN]                      : consumed before z is written
//   - z   [NTV,CC]   (start of buffer)   : consumed before big is reused
// ---------------------------------------------------------------------------
__device__ float g_big [NTV * CATN];       // 315 MB
__device__ float g_preA[NTV * CC];         // 105 MB : pre-LN buffer A
__device__ float g_preB[NTV * CC];         // 105 MB : pre-LN buffer B (zb path)
__device__ float g_y   [NTV * CC];         // 105 MB : y after spatial block
__device__ float g_atts[NN * SS * VV * VV];
__device__ float g_attt[NN * SS * TT * TT];

__device__ __forceinline__ float gelu_f(float x) {
    return 0.5f * x * (1.0f + erff(x * 0.70710678118654752f));
}

// ---------------------------------------------------------------------------
// Generic SGEMM:  C[M,Nc] = epi(A[M,K] @ B[K,Nc] + bias)
// BM=BN=64, BK=16, 256 threads, 4x4 per-thread microtile.
// Requires M%64==0, Nc%64==0, K%16==0 (true for all call sites).
// EPI: 0 = bias only, 1 = elu(v)+1  (v>0 ? v+1 : exp(v))
// ---------------------------------------------------------------------------
template<int EPI>
__global__ void sgemm_kernel(const float* __restrict__ A,
                             const float* __restrict__ B,
                             const float* __restrict__ bias,
                             float* __restrict__ C,
                             int M, int K, int Nc) {
    __shared__ float As[16][64];   // transposed: As[kk][row]
    __shared__ float Bs[16][64];

    const int tid = threadIdx.x;
    const int tx = tid & 15;       // 0..15  -> 4 cols each
    const int ty = tid >> 4;       // 0..15  -> 4 rows each
    const int bm = blockIdx.y;
    const int bn = blockIdx.x;

    float acc[4][4];
    #pragma unroll
    for (int i = 0; i < 4; i++)
        #pragma unroll
        for (int j = 0; j < 4; j++) acc[i][j] = 0.f;

    const int a_row = tid >> 2;          // 0..63
    const int a_c4  = (tid & 3) * 4;     // 0,4,8,12
    const int b_row = tid >> 4;          // 0..15
    const int b_c4  = (tid & 15) * 4;    // 0..60

    const float* Aptr = A + (long)(bm * 64 + a_row) * K + a_c4;
    const float* Bptr = B + (long)b_row * Nc + bn * 64 + b_c4;

    for (int k0 = 0; k0 < K; k0 += 16) {
        float4 av = *(const float4*)(Aptr + k0);
        float4 bv = *(const float4*)(Bptr + (long)k0 * Nc);
        As[a_c4 + 0][a_row] = av.x;
        As[a_c4 + 1][a_row] = av.y;
        As[a_c4 + 2][a_row] = av.z;
        As[a_c4 + 3][a_row] = av.w;
        *(float4*)&Bs[b_row][b_c4] = bv;
        __syncthreads();

        #pragma unroll
        for (int kk = 0; kk < 16; kk++) {
            float4 a4 = *(const float4*)&As[kk][ty * 4];
            float4 b4 = *(const float4*)&Bs[kk][tx * 4];
            acc[0][0] += a4.x * b4.x; acc[0][1] += a4.x * b4.y;
            acc[0][2] += a4.x * b4.z; acc[0][3] += a4.x * b4.w;
            acc[1][0] += a4.y * b4.x; acc[1][1] += a4.y * b4.y;
            acc[1][2] += a4.y * b4.z; acc[1][3] += a4.y * b4.w;
            acc[2][0] += a4.z * b4.x; acc[2][1] += a4.z * b4.y;
            acc[2][2] += a4.z * b4.z; acc[2][3] += a4.z * b4.w;
            acc[3][0] += a4.w * b4.x; acc[3][1] += a4.w * b4.y;
            acc[3][2] += a4.w * b4.z; acc[3][3] += a4.w * b4.w;
        }
        __syncthreads();
    }

    const int row0 = bm * 64 + ty * 4;
    const int col0 = bn * 64 + tx * 4;
    float4 bb = *(const float4*)(bias + col0);
    #pragma unroll
    for (int i = 0; i < 4; i++) {
        float4 o;
        o.x = acc[i][0] + bb.x;
        o.y = acc[i][1] + bb.y;
        o.z = acc[i][2] + bb.z;
        o.w = acc[i][3] + bb.w;
        if (EPI == 1) {
            o.x = o.x > 0.f ? o.x + 1.f : __expf(o.x);
            o.y = o.y > 0.f ? o.y + 1.f : __expf(o.y);
            o.z = o.z > 0.f ? o.z + 1.f : __expf(o.z);
            o.w = o.w > 0.f ? o.w + 1.f : __expf(o.w);
        }
        *(float4*)&C[(long)(row0 + i) * Nc + col0] = o;
    }
}

// ---------------------------------------------------------------------------
// Spatial attention: att[n,s,v,u] = norm_u( sum_{t,ic} q k ) + att0[s,v,u]
// One block per (n,s); 256 threads; each thread owns up to 3 of 625 outputs.
// (The /(IC*t) scale cancels under the row-sum normalization.)
// ---------------------------------------------------------------------------
__global__ void spatial_att_kernel(const float* __restrict__ qk,
                                   const float* __restrict__ att0,
                                   float* __restrict__ att) {
    const int n = blockIdx.x / SS;
    const int s = blockIdx.x % SS;
    const int tid = threadIdx.x;

    __shared__ float qs[VV][65];
    __shared__ float ks[VV][65];
    __shared__ float osh[VV * VV];
    __shared__ float rsum[VV];

    float acc[3] = {0.f, 0.f, 0.f};

    for (int t = 0; t < TT; t++) {
        for (int idx = tid; idx < VV * ICC; idx += 256) {
            int v  = idx >> 6;
            int ic = idx & 63;
            int base = ((n * TT + t) * VV + v) * QKN + ic * (2 * SS);
            qs[v][ic] = qk[base + s];
            ks[v][ic] = qk[base + s + SS];
        }
        __syncthreads();
        #pragma unroll
        for (int j = 0; j < 3; j++) {
            int o = tid + j * 256;
            if (o < VV * VV) {
                int v = o / VV, u = o % VV;
                float a = acc[j];
                #pragma unroll
                for (int ic = 0; ic < ICC; ic++) a += qs[v][ic] * ks[u][ic];
                acc[j] = a;
            }
        }
        __syncthreads();
    }
    #pragma unroll
    for (int j = 0; j < 3; j++) {
        int o = tid + j * 256;
        if (o < VV * VV) osh[o] = acc[j];
    }
    __syncthreads();
    if (tid < VV) {
        float sm = 0.f;
        #pragma unroll
        for (int u = 0; u < VV; u++) sm += osh[tid * VV + u];
        rsum[tid] = sm;
    }
    __syncthreads();
    #pragma unroll
    for (int j = 0; j < 3; j++) {
        int o = tid + j * 256;
        if (o < VV * VV) {
            int v = o / VV;
            att[(n * SS + s) * (VV * VV) + o] =
                osh[o] / rsum[v] + att0[s * (VV * VV) + o];
        }
    }
}

// ---------------------------------------------------------------------------
// Spatial apply: ycat[n,t,v, c*3+s] = sum_u att[n,s,v,u] * x[n,t,u,c]
// One block per (n,t); 256 threads = one channel c each.
// ---------------------------------------------------------------------------
__global__ void spatial_apply_kernel(const float* __restrict__ att,
                                     const float* __restrict__ x,
                                     float* __restrict__ ycat) {
    const int n = blockIdx.x / TT;
    const int t = blockIdx.x % TT;
    const int tid = threadIdx.x;

    __shared__ float xs[VV][CC];               // 25.6 KB
    __shared__ float as[SS][VV][VV];           // 7.5 KB

    for (int idx = tid; idx < VV * CC; idx += 256) {
        int u = idx >> 8, c = idx & 255;
        xs[u][c] = x[((n * TT + t) * VV + u) * CC + c];
    }
    for (int idx = tid; idx < SS * VV * VV; idx += 256)
        ((float*)as)[idx] = att[n * SS * VV * VV + idx];
    __syncthreads();

    const int c = tid;
    for (int v = 0; v < VV; v++) {
        float a0 = 0.f, a1 = 0.f, a2 = 0.f;
        #pragma unroll
        for (int u = 0; u < VV; u++) {
            float xv = xs[u][c];
            a0 += as[0][v][u] * xv;
            a1 += as[1][v][u] * xv;
            a2 += as[2][v][u] * xv;
        }
        int base = ((n * TT + t) * VV + v) * CATN + c * 3;
        ycat[base + 0] = a0;
        ycat[base + 1] = a1;
        ycat[base + 2] = a2;
    }
}

// ---------------------------------------------------------------------------
// Temporal attention: a[n,s,t,k] = norm_k( mask * sum_{v,ic} q k )
// One block per (n,s); each thread owns 4 of 1024 outputs.
// ---------------------------------------------------------------------------
__global__ void temporal_att_kernel(const float* __restrict__ qk,
                                    float* __restrict__ att,
                                    int forward) {
    const int n = blockIdx.x / SS;
    const int s = blockIdx.x % SS;
    const int tid = threadIdx.x;

    __shared__ float qs[TT][65];
    __shared__ float ks[TT][65];
    __shared__ float osh[TT][TT + 1];
    __shared__ float rsum[TT];

    float acc[4] = {0.f, 0.f, 0.f, 0.f};

    for (int v = 0; v < VV; v++) {
        for (int idx = tid; idx < TT * ICC; idx += 256) {
            int t  = idx >> 6;
            int ic = idx & 63;
            int base = ((n * TT + t) * VV + v) * QKN + ic * (2 * SS);
            qs[t][ic] = qk[base + s];
            ks[t][ic] = qk[base + s + SS];
        }
        __syncthreads();
        #pragma unroll
        for (int j = 0; j < 4; j++) {
            int o = tid + j * 256;
            int t = o >> 5, k2 = o & 31;
            float a = acc[j];
            #pragma unroll
            for (int ic = 0; ic < ICC; ic++) a += qs[t][ic] * ks[k2][ic];
            acc[j] = a;
        }
        __syncthreads();
    }
    #pragma unroll
    for (int j = 0; j < 4; j++) {
        int o = tid + j * 256;
        int t = o >> 5, k2 = o & 31;
        bool keep = forward ? (k2 <= t) : (k2 >= t);
        osh[t][k2] = keep ? acc[j] : 0.f;
    }
    __syncthreads();
    if (tid < TT) {
        float sm = 0.f;
        #pragma unroll
        for (int k2 = 0; k2 < TT; k2++) sm += osh[tid][k2];
        rsum[tid] = sm;
    }
    __syncthreads();
    #pragma unroll
    for (int j = 0; j < 4; j++) {
        int o = tid + j * 256;
        int t = o >> 5, k2 = o & 31;
        att[(n * SS + s) * (TT * TT) + o] = osh[t][k2] / rsum[t];
    }
}

// ---------------------------------------------------------------------------
// Temporal apply: zcat[n,t,v, c*3+s] = sum_k a[n,s,t,k] * y[n,k,v,c]
// One block per (n,v).
// ---------------------------------------------------------------------------
__global__ void temporal_apply_kernel(const float* __restrict__ att,
                                      const float* __restrict__ y,
                                      float* __restrict__ zcat) {
    const int n = blockIdx.x / VV;
    const int v = blockIdx.x % VV;
    const int tid = threadIdx.x;

    __shared__ float ys[TT][CC];               // 32 KB
    __shared__ float as[SS][TT][TT];           // 12 KB

    for (int idx = tid; idx < TT * CC; idx += 256) {
        int k = idx >> 8, c = idx & 255;
        ys[k][c] = y[((n * TT + k) * VV + v) * CC + c];
    }
    for (int idx = tid; idx < SS * TT * TT; idx += 256)
        ((float*)as)[idx] = att[n * SS * TT * TT + idx];
    __syncthreads();

    const int c = tid;
    for (int t = 0; t < TT; t++) {
        float a0 = 0.f, a1 = 0.f, a2 = 0.f;
        #pragma unroll
        for (int k = 0; k < TT; k++) {
            float yv = ys[k][c];
            a0 += as[0][t][k] * yv;
            a1 += as[1][t][k] * yv;
            a2 += as[2][t][k] * yv;
        }
        int base = ((n * TT + t) * VV + v) * CATN + c * 3;
        zcat[base + 0] = a0;
        zcat[base + 1] = a1;
        zcat[base + 2] = a2;
    }
}

// ---------------------------------------------------------------------------
// Fused LayerNorm (+residual +GELU). One 256-thread block per row (C=256).
// Uses E[v^2]-mean^2 (single pass); inputs are O(1) so this is safe in fp32.
// ---------------------------------------------------------------------------
__global__ void ln_add_gelu2_kernel(const float* __restrict__ pre,
                                    const float* __restrict__ resid,
                                    float* __restrict__ out) {
    __shared__ float red[16];
    const int row = blockIdx.x;
    const int tid = threadIdx.x;
    const long idx = (long)row * CC + tid;

    float v = pre[idx];
    float s1 = v, s2 = v * v;
    #pragma unroll
    for (int o = 16; o > 0; o >>= 1) {
        s1 += __shfl_xor_sync(0xFFFFFFFFu, s1, o);
        s2 += __shfl_xor_sync(0xFFFFFFFFu, s2, o);
    }
    if ((tid & 31) == 0) { red[tid >> 5] = s1; red[8 + (tid >> 5)] = s2; }
    __syncthreads();
    float t1 = 0.f, t2 = 0.f;
    #pragma unroll
    for (int i = 0; i < 8; i++) { t1 += red[i]; t2 += red[8 + i]; }
    float mean = t1 * (1.0f / CC);
    float var  = t2 * (1.0f / CC) - mean * mean;
    float ln   = (v - mean) * rsqrtf(var + LN_EPS);

    out[idx] = gelu_f(resid[idx] + ln);
}

// out = gelu(y + LN(preF) + LN(preB)) — the z_f + z_b combine, fused.
__global__ void ln2_add_gelu3_kernel(const float* __restrict__ preF,
                                     const float* __restrict__ preB,
                                     const float* __restrict__ y,
                                     float* __restrict__ out) {
    __shared__ float red[32];
    const int row = blockIdx.x;
    const int tid = threadIdx.x;
    const long idx = (long)row * CC + tid;

    float vf = preF[idx];
    float vb = preB[idx];
    float s1 = vf, s2 = vf * vf, s3 = vb, s4 = vb * vb;
    #pragma unroll
    for (int o = 16; o > 0; o >>= 1) {
        s1 += __shfl_xor_sync(0xFFFFFFFFu, s1, o);
        s2 += __shfl_xor_sync(0xFFFFFFFFu, s2, o);
        s3 += __shfl_xor_sync(0xFFFFFFFFu, s3, o);
        s4 += __shfl_xor_sync(0xFFFFFFFFu, s4, o);
    }
    if ((tid & 31) == 0) {
        int w = tid >> 5;
        red[w] = s1; red[8 + w] = s2; red[16 + w] = s3; red[24 + w] = s4;
    }
    __syncthreads();
    float t1 = 0.f, t2 = 0.f, t3 = 0.f, t4 = 0.f;
    #pragma unroll
    for (int i = 0; i < 8; i++) {
        t1 += red[i]; t2 += red[8 + i]; t3 += red[16 + i]; t4 += red[24 + i];
    }
    float mf = t1 * (1.0f / CC);
    float lf = (vf - mf) * rsqrtf(t2 * (1.0f / CC) - mf * mf + LN_EPS);
    float mb = t3 * (1.0f / CC);
    float lb = (vb - mb) * rsqrtf(t4 * (1.0f / CC) - mb * mb + LN_EPS);

    out[idx] = gelu_f(y[idx] + lf + lb);
}

// ---------------------------------------------------------------------------
// Host orchestration
// ---------------------------------------------------------------------------
static float* sym_addr(const void* sym) {
    void* p = 0;
    cudaGetSymbolAddress(&p, sym);
    return (float*)p;
}

extern "C" void kernel_launch(void* const* d_in, const int* in_sizes, int n_in,
                              void* d_out, int out_size) {
    const float* x        = (const float*)d_in[0];
    const float* Win_s    = (const float*)d_in[1];
    const float* bin_s    = (const float*)d_in[2];
    const float* att0     = (const float*)d_in[3];
    const float* Wout_s   = (const float*)d_in[4];
    const float* bout_s   = (const float*)d_in[5];
    const float* Wff_s    = (const float*)d_in[6];
    const float* bff_s    = (const float*)d_in[7];
    const float* Win_tf   = (const float*)d_in[8];
    const float* bin_tf   = (const float*)d_in[9];
    const float* Win_tb   = (const float*)d_in[10];
    const float* bin_tb   = (const float*)d_in[11];
    const float* Wout_tf  = (const float*)d_in[12];
    const float* bout_tf  = (const float*)d_in[13];
    const float* Wout_tb  = (const float*)d_in[14];
    const float* bout_tb  = (const float*)d_in[15];
    const float* Wff_t    = (const float*)d_in[16];
    const float* bff_t    = (const float*)d_in[17];
    float* out = (float*)d_out;

    float* big  = sym_addr(g_big);
    float* preA = sym_addr(g_preA);
    float* preB = sym_addr(g_preB);
    float* ybuf = sym_addr(g_y);
    float* atts = sym_addr(g_atts);
    float* attt = sym_addr(g_attt);

    float* qk   = big;   // [NTV,QKN]  alias — consumed before cat is written
    float* cat  = big;   // [NTV,CATN]
    float* zbuf = big;   // [NTV,CC]   alias — cat fully consumed before write

    const dim3 blk(256);
    const dim3 g_in(QKN / 64, NTV / 64);     // 6 x 1600
    const dim3 g_out(CC / 64, NTV / 64);     // 4 x 1600

    // ---- spatial block ----
    sgemm_kernel<1><<<g_in, blk>>>(x, Win_s, bin_s, qk, NTV, CC, QKN);
    spatial_att_kernel<<<NN * SS, blk>>>(qk, att0, atts);
    spatial_apply_kernel<<<NN * TT, blk>>>(atts, x, cat);
    sgemm_kernel<0><<<g_out, blk>>>(cat, Wout_s, bout_s, preA, NTV, CATN, CC);
    ln_add_gelu2_kernel<<<NTV, 256>>>(preA, x, ybuf);
    sgemm_kernel<0><<<g_out, blk>>>(ybuf, Wff_s, bff_s, preA, NTV, CC, CC);
    ln_add_gelu2_kernel<<<NTV, 256>>>(preA, x, ybuf);

    // ---- temporal forward ----
    sgemm_kernel<1><<<g_in, blk>>>(ybuf, Win_tf, bin_tf, qk, NTV, CC, QKN);
    temporal_att_kernel<<<NN * SS, blk>>>(qk, attt, 1);
    temporal_apply_kernel<<<NN * VV, blk>>>(attt, ybuf, cat);
    sgemm_kernel<0><<<g_out, blk>>>(cat, Wout_tf, bout_tf, preA, NTV, CATN, CC);

    // ---- temporal backward ----
    sgemm_kernel<1><<<g_in, blk>>>(ybuf, Win_tb, bin_tb, qk, NTV, CC, QKN);
    temporal_att_kernel<<<NN * SS, blk>>>(qk, attt, 0);
    temporal_apply_kernel<<<NN * VV, blk>>>(attt, ybuf, cat);
    sgemm_kernel<0><<<g_out, blk>>>(cat, Wout_tb, bout_tb, preB, NTV, CATN, CC);

    // ---- combine + final FF ----
    ln2_add_gelu3_kernel<<<NTV, 256>>>(preA, preB, ybuf, zbuf);
    sgemm_kernel<0><<<g_out, blk>>>(zbuf, Wff_t, bff_t, preA, NTV, CC, CC);
    ln_add_gelu2_kernel<<<NTV, 256>>>(preA, ybuf, out);
}

// round 4
// speedup vs baseline: 1.3310x; 1.3310x over previous
#include <cuda_runtime.h>
#include <math.h>

// Problem constants
#define NN   128
#define TT   32
#define VV   25
#define CC   256
#define ICC  64
#define SS   3
#define NTV  (NN*TT*VV)        // 102400 rows
#define QKN  (2*SS*ICC)        // 384
#define CATN (SS*CC)           // 768
#define LN_EPS 1e-5f

// ---------------------------------------------------------------------------
// Scratch (device globals; allocations are forbidden). ~630 MB total.
// g_big [NTV,CATN] holds, at different times:
//   - qk  [NTV,QKN]  (start of buffer)   : consumed before cat is written
//   - cat [NTV,CATN]                      : consumed before z is written
//   - z   [NTV,CC]   (start of buffer)   : consumed before big is reused
// ---------------------------------------------------------------------------
__device__ float g_big [NTV * CATN];       // 315 MB
__device__ float g_preA[NTV * CC];         // 105 MB : pre-LN buffer A
__device__ float g_preB[NTV * CC];         // 105 MB : pre-LN buffer B (zb path)
__device__ float g_y   [NTV * CC];         // 105 MB : y after spatial block
__device__ float g_atts[NN * SS * VV * VV];
__device__ float g_attt[NN * SS * TT * TT];

__device__ __forceinline__ float gelu_f(float x) {
    return 0.5f * x * (1.0f + erff(x * 0.70710678118654752f));
}

// ---------------------------------------------------------------------------
// Packed f32x2 helpers (Blackwell FFMA2 — only reachable via inline PTX)
// ---------------------------------------------------------------------------
__device__ __forceinline__ unsigned long long dup_f32(float a) {
    unsigned long long d;
    asm("mov.b64 %0, {%1, %1};" : "=l"(d) : "f"(a));
    return d;
}
__device__ __forceinline__ unsigned long long pack_f32(float x, float y) {
    unsigned long long d;
    asm("mov.b64 %0, {%1, %2};" : "=l"(d) : "f"(x), "f"(y));
    return d;
}
__device__ __forceinline__ void ffma2(unsigned long long& acc,
                                      unsigned long long a,
                                      unsigned long long b) {
    asm("fma.rn.f32x2 %0, %1, %2, %0;" : "+l"(acc) : "l"(a), "l"(b));
}
__device__ __forceinline__ float2 unpack_f32(unsigned long long d) {
    float2 r;
    asm("mov.b64 {%0, %1}, %2;" : "=f"(r.x), "=f"(r.y) : "l"(d));
    return r;
}

// ---------------------------------------------------------------------------
// SGEMM:  C[M,Nc] = epi(A[M,K] @ B[K,Nc] + bias)
// BM=BN=128, BK=16, 256 threads, 8x8 microtile (as 2x2 of 4x4 sub-tiles at
// +0/+64 offsets -> phase-conflict-free LDS.128), double-buffered smem,
// FFMA2 (f32x2) accumulation: acc[8][4] 64-bit pairs.
// Requires M%128==0, Nc%128==0, K%16==0 (true for all call sites).
// EPI: 0 = bias only, 1 = elu(v)+1  (v>0 ? v+1 : exp(v))
// ---------------------------------------------------------------------------
template<int EPI>
__global__ __launch_bounds__(256)
void sgemm_kernel(const float* __restrict__ A,
                  const float* __restrict__ B,
                  const float* __restrict__ bias,
                  float* __restrict__ C,
                  int M, int K, int Nc) {
    __shared__ float As[2][16][128];   // transposed: As[buf][kk][row]
    __shared__ float Bs[2][16][128];

    const int tid = threadIdx.x;
    const int tx = tid & 15;           // 0..15 -> cols tx*4 and tx*4+64
    const int ty = tid >> 4;           // 0..15 -> rows ty*4 and ty*4+64
    const int bm = blockIdx.y;
    const int bn = blockIdx.x;

    unsigned long long acc[8][4];
    #pragma unroll
    for (int i = 0; i < 8; i++)
        #pragma unroll
        for (int j = 0; j < 4; j++) acc[i][j] = 0ULL;

    // Global-load assignments
    const int a_row = tid >> 2;          // 0..63 (also +64)
    const int a_c4  = (tid & 3) * 4;     // 0,4,8,12
    const int b_kk  = tid >> 4;          // 0..15
    const int b_c4  = (tid & 15) * 4;    // 0..60 (also +64)

    const float* Ap0 = A + (long)(bm * 128 + a_row)      * K + a_c4;
    const float* Ap1 = A + (long)(bm * 128 + a_row + 64) * K + a_c4;
    const float* Bp  = B + (long)b_kk * Nc + bn * 128 + b_c4;

    // Prologue: load tile 0 into buffer 0
    {
        float4 av0 = *(const float4*)(Ap0);
        float4 av1 = *(const float4*)(Ap1);
        float4 bv0 = *(const float4*)(Bp);
        float4 bv1 = *(const float4*)(Bp + 64);
        As[0][a_c4 + 0][a_row] = av0.x;  As[0][a_c4 + 1][a_row] = av0.y;
        As[0][a_c4 + 2][a_row] = av0.z;  As[0][a_c4 + 3][a_row] = av0.w;
        As[0][a_c4 + 0][a_row + 64] = av1.x;  As[0][a_c4 + 1][a_row + 64] = av1.y;
        As[0][a_c4 + 2][a_row + 64] = av1.z;  As[0][a_c4 + 3][a_row + 64] = av1.w;
        *(float4*)&Bs[0][b_kk][b_c4]      = bv0;
        *(float4*)&Bs[0][b_kk][b_c4 + 64] = bv1;
    }
    __syncthreads();

    int buf = 0;
    for (int k0 = 0; k0 < K; k0 += 16) {
        const bool has_next = (k0 + 16) < K;
        float4 av0n, av1n, bv0n, bv1n;
        if (has_next) {
            av0n = *(const float4*)(Ap0 + k0 + 16);
            av1n = *(const float4*)(Ap1 + k0 + 16);
            bv0n = *(const float4*)(Bp + (long)(k0 + 16) * Nc);
            bv1n = *(const float4*)(Bp + (long)(k0 + 16) * Nc + 64);
        }

        #pragma unroll
        for (int kk = 0; kk < 16; kk++) {
            float4 a4l = *(const float4*)&As[buf][kk][ty * 4];
            float4 a4h = *(const float4*)&As[buf][kk][64 + ty * 4];
            float4 b4l = *(const float4*)&Bs[buf][kk][tx * 4];
            float4 b4h = *(const float4*)&Bs[buf][kk][64 + tx * 4];

            unsigned long long bp[4];
            bp[0] = pack_f32(b4l.x, b4l.y);
            bp[1] = pack_f32(b4l.z, b4l.w);
            bp[2] = pack_f32(b4h.x, b4h.y);
            bp[3] = pack_f32(b4h.z, b4h.w);

            unsigned long long ad[8];
            ad[0] = dup_f32(a4l.x); ad[1] = dup_f32(a4l.y);
            ad[2] = dup_f32(a4l.z); ad[3] = dup_f32(a4l.w);
            ad[4] = dup_f32(a4h.x); ad[5] = dup_f32(a4h.y);
            ad[6] = dup_f32(a4h.z); ad[7] = dup_f32(a4h.w);

            #pragma unroll
            for (int r = 0; r < 8; r++) {
                ffma2(acc[r][0], ad[r], bp[0]);
                ffma2(acc[r][1], ad[r], bp[1]);
                ffma2(acc[r][2], ad[r], bp[2]);
                ffma2(acc[r][3], ad[r], bp[3]);
            }
        }

        if (has_next) {
            int nb = buf ^ 1;
            As[nb][a_c4 + 0][a_row] = av0n.x;  As[nb][a_c4 + 1][a_row] = av0n.y;
            As[nb][a_c4 + 2][a_row] = av0n.z;  As[nb][a_c4 + 3][a_row] = av0n.w;
            As[nb][a_c4 + 0][a_row + 64] = av1n.x;  As[nb][a_c4 + 1][a_row + 64] = av1n.y;
            As[nb][a_c4 + 2][a_row + 64] = av1n.z;  As[nb][a_c4 + 3][a_row + 64] = av1n.w;
            *(float4*)&Bs[nb][b_kk][b_c4]      = bv0n;
            *(float4*)&Bs[nb][b_kk][b_c4 + 64] = bv1n;
        }
        __syncthreads();
        buf ^= 1;
    }

    // Epilogue
    const int col_l = bn * 128 + tx * 4;
    const int col_h = col_l + 64;
    float4 bb_l = *(const float4*)(bias + col_l);
    float4 bb_h = *(const float4*)(bias + col_h);

    #pragma unroll
    for (int r = 0; r < 8; r++) {
        const int row = bm * 128 + ((r < 4) ? (ty * 4 + r) : (64 + ty * 4 + r - 4));
        float2 p0 = unpack_f32(acc[r][0]);
        float2 p1 = unpack_f32(acc[r][1]);
        float2 p2 = unpack_f32(acc[r][2]);
        float2 p3 = unpack_f32(acc[r][3]);
        float4 ol, oh;
        ol.x = p0.x + bb_l.x;  ol.y = p0.y + bb_l.y;
        ol.z = p1.x + bb_l.z;  ol.w = p1.y + bb_l.w;
        oh.x = p2.x + bb_h.x;  oh.y = p2.y + bb_h.y;
        oh.z = p3.x + bb_h.z;  oh.w = p3.y + bb_h.w;
        if (EPI == 1) {
            ol.x = ol.x > 0.f ? ol.x + 1.f : __expf(ol.x);
            ol.y = ol.y > 0.f ? ol.y + 1.f : __expf(ol.y);
            ol.z = ol.z > 0.f ? ol.z + 1.f : __expf(ol.z);
            ol.w = ol.w > 0.f ? ol.w + 1.f : __expf(ol.w);
            oh.x = oh.x > 0.f ? oh.x + 1.f : __expf(oh.x);
            oh.y = oh.y > 0.f ? oh.y + 1.f : __expf(oh.y);
            oh.z = oh.z > 0.f ? oh.z + 1.f : __expf(oh.z);
            oh.w = oh.w > 0.f ? oh.w + 1.f : __expf(oh.w);
        }
        *(float4*)&C[(long)row * Nc + col_l] = ol;
        *(float4*)&C[(long)row * Nc + col_h] = oh;
    }
}

// ---------------------------------------------------------------------------
// Spatial attention: att[n,s,v,u] = norm_u( sum_{t,ic} q k ) + att0[s,v,u]
// One block per (n,s); 256 threads; each thread owns up to 3 of 625 outputs.
// (The /(IC*t) scale cancels under the row-sum normalization.)
// ---------------------------------------------------------------------------
__global__ void spatial_att_kernel(const float* __restrict__ qk,
                                   const float* __restrict__ att0,
                                   float* __restrict__ att) {
    const int n = blockIdx.x / SS;
    const int s = blockIdx.x % SS;
    const int tid = threadIdx.x;

    __shared__ float qs[VV][65];
    __shared__ float ks[VV][65];
    __shared__ float osh[VV * VV];
    __shared__ float rsum[VV];

    float acc[3] = {0.f, 0.f, 0.f};

    for (int t = 0; t < TT; t++) {
        for (int idx = tid; idx < VV * ICC; idx += 256) {
            int v  = idx >> 6;
            int ic = idx & 63;
            int base = ((n * TT + t) * VV + v) * QKN + ic * (2 * SS);
            qs[v][ic] = qk[base + s];
            ks[v][ic] = qk[base + s + SS];
        }
        __syncthreads();
        #pragma unroll
        for (int j = 0; j < 3; j++) {
            int o = tid + j * 256;
            if (o < VV * VV) {
                int v = o / VV, u = o % VV;
                float a = acc[j];
                #pragma unroll
                for (int ic = 0; ic < ICC; ic++) a += qs[v][ic] * ks[u][ic];
                acc[j] = a;
            }
        }
        __syncthreads();
    }
    #pragma unroll
    for (int j = 0; j < 3; j++) {
        int o = tid + j * 256;
        if (o < VV * VV) osh[o] = acc[j];
    }
    __syncthreads();
    if (tid < VV) {
        float sm = 0.f;
        #pragma unroll
        for (int u = 0; u < VV; u++) sm += osh[tid * VV + u];
        rsum[tid] = sm;
    }
    __syncthreads();
    #pragma unroll
    for (int j = 0; j < 3; j++) {
        int o = tid + j * 256;
        if (o < VV * VV) {
            int v = o / VV;
            att[(n * SS + s) * (VV * VV) + o] =
                osh[o] / rsum[v] + att0[s * (VV * VV) + o];
        }
    }
}

// ---------------------------------------------------------------------------
// Spatial apply: ycat[n,t,v, c*3+s] = sum_u att[n,s,v,u] * x[n,t,u,c]
// One block per (n,t); 256 threads = one channel c each.
// ---------------------------------------------------------------------------
__global__ void spatial_apply_kernel(const float* __restrict__ att,
                                     const float* __restrict__ x,
                                     float* __restrict__ ycat) {
    const int n = blockIdx.x / TT;
    const int t = blockIdx.x % TT;
    const int tid = threadIdx.x;

    __shared__ float xs[VV][CC];               // 25.6 KB
    __shared__ float as[SS][VV][VV];           // 7.5 KB

    for (int idx = tid; idx < VV * CC; idx += 256) {
        int u = idx >> 8, c = idx & 255;
        xs[u][c] = x[((n * TT + t) * VV + u) * CC + c];
    }
    for (int idx = tid; idx < SS * VV * VV; idx += 256)
        ((float*)as)[idx] = att[n * SS * VV * VV + idx];
    __syncthreads();

    const int c = tid;
    for (int v = 0; v < VV; v++) {
        float a0 = 0.f, a1 = 0.f, a2 = 0.f;
        #pragma unroll
        for (int u = 0; u < VV; u++) {
            float xv = xs[u][c];
            a0 += as[0][v][u] * xv;
            a1 += as[1][v][u] * xv;
            a2 += as[2][v][u] * xv;
        }
        int base = ((n * TT + t) * VV + v) * CATN + c * 3;
        ycat[base + 0] = a0;
        ycat[base + 1] = a1;
        ycat[base + 2] = a2;
    }
}

// ---------------------------------------------------------------------------
// Temporal attention: a[n,s,t,k] = norm_k( mask * sum_{v,ic} q k )
// One block per (n,s); each thread owns 4 of 1024 outputs.
// ---------------------------------------------------------------------------
__global__ void temporal_att_kernel(const float* __restrict__ qk,
                                    float* __restrict__ att,
                                    int forward) {
    const int n = blockIdx.x / SS;
    const int s = blockIdx.x % SS;
    const int tid = threadIdx.x;

    __shared__ float qs[TT][65];
    __shared__ float ks[TT][65];
    __shared__ float osh[TT][TT + 1];
    __shared__ float rsum[TT];

    float acc[4] = {0.f, 0.f, 0.f, 0.f};

    for (int v = 0; v < VV; v++) {
        for (int idx = tid; idx < TT * ICC; idx += 256) {
            int t  = idx >> 6;
            int ic = idx & 63;
            int base = ((n * TT + t) * VV + v) * QKN + ic * (2 * SS);
            qs[t][ic] = qk[base + s];
            ks[t][ic] = qk[base + s + SS];
        }
        __syncthreads();
        #pragma unroll
        for (int j = 0; j < 4; j++) {
            int o = tid + j * 256;
            int t = o >> 5, k2 = o & 31;
            float a = acc[j];
            #pragma unroll
            for (int ic = 0; ic < ICC; ic++) a += qs[t][ic] * ks[k2][ic];
            acc[j] = a;
        }
        __syncthreads();
    }
    #pragma unroll
    for (int j = 0; j < 4; j++) {
        int o = tid + j * 256;
        int t = o >> 5, k2 = o & 31;
        bool keep = forward ? (k2 <= t) : (k2 >= t);
        osh[t][k2] = keep ? acc[j] : 0.f;
    }
    __syncthreads();
    if (tid < TT) {
        float sm = 0.f;
        #pragma unroll
        for (int k2 = 0; k2 < TT; k2++) sm += osh[tid][k2];
        rsum[tid] = sm;
    }
    __syncthreads();
    #pragma unroll
    for (int j = 0; j < 4; j++) {
        int o = tid + j * 256;
        int t = o >> 5, k2 = o & 31;
        att[(n * SS + s) * (TT * TT) + o] = osh[t][k2] / rsum[t];
    }
}

// ---------------------------------------------------------------------------
// Temporal apply: zcat[n,t,v, c*3+s] = sum_k a[n,s,t,k] * y[n,k,v,c]
// One block per (n,v).
// ---------------------------------------------------------------------------
__global__ void temporal_apply_kernel(const float* __restrict__ att,
                                      const float* __restrict__ y,
                                      float* __restrict__ zcat) {
    const int n = blockIdx.x / VV;
    const int v = blockIdx.x % VV;
    const int tid = threadIdx.x;

    __shared__ float ys[TT][CC];               // 32 KB
    __shared__ float as[SS][TT][TT];           // 12 KB

    for (int idx = tid; idx < TT * CC; idx += 256) {
        int k = idx >> 8, c = idx & 255;
        ys[k][c] = y[((n * TT + k) * VV + v) * CC + c];
    }
    for (int idx = tid; idx < SS * TT * TT; idx += 256)
        ((float*)as)[idx] = att[n * SS * TT * TT + idx];
    __syncthreads();

    const int c = tid;
    for (int t = 0; t < TT; t++) {
        float a0 = 0.f, a1 = 0.f, a2 = 0.f;
        #pragma unroll
        for (int k = 0; k < TT; k++) {
            float yv = ys[k][c];
            a0 += as[0][t][k] * yv;
            a1 += as[1][t][k] * yv;
            a2 += as[2][t][k] * yv;
        }
        int base = ((n * TT + t) * VV + v) * CATN + c * 3;
        zcat[base + 0] = a0;
        zcat[base + 1] = a1;
        zcat[base + 2] = a2;
    }
}

// ---------------------------------------------------------------------------
// Fused LayerNorm (+residual +GELU). One 256-thread block per row (C=256).
// ---------------------------------------------------------------------------
__global__ void ln_add_gelu2_kernel(const float* __restrict__ pre,
                                    const float* __restrict__ resid,
                                    float* __restrict__ out) {
    __shared__ float red[16];
    const int row = blockIdx.x;
    const int tid = threadIdx.x;
    const long idx = (long)row * CC + tid;

    float v = pre[idx];
    float s1 = v, s2 = v * v;
    #pragma unroll
    for (int o = 16; o > 0; o >>= 1) {
        s1 += __shfl_xor_sync(0xFFFFFFFFu, s1, o);
        s2 += __shfl_xor_sync(0xFFFFFFFFu, s2, o);
    }
    if ((tid & 31) == 0) { red[tid >> 5] = s1; red[8 + (tid >> 5)] = s2; }
    __syncthreads();
    float t1 = 0.f, t2 = 0.f;
    #pragma unroll
    for (int i = 0; i < 8; i++) { t1 += red[i]; t2 += red[8 + i]; }
    float mean = t1 * (1.0f / CC);
    float var  = t2 * (1.0f / CC) - mean * mean;
    float ln   = (v - mean) * rsqrtf(var + LN_EPS);

    out[idx] = gelu_f(resid[idx] + ln);
}

// out = gelu(y + LN(preF) + LN(preB)) — the z_f + z_b combine, fused.
__global__ void ln2_add_gelu3_kernel(const float* __restrict__ preF,
                                     const float* __restrict__ preB,
                                     const float* __restrict__ y,
                                     float* __restrict__ out) {
    __shared__ float red[32];
    const int row = blockIdx.x;
    const int tid = threadIdx.x;
    const long idx = (long)row * CC + tid;

    float vf = preF[idx];
    float vb = preB[idx];
    float s1 = vf, s2 = vf * vf, s3 = vb, s4 = vb * vb;
    #pragma unroll
    for (int o = 16; o > 0; o >>= 1) {
        s1 += __shfl_xor_sync(0xFFFFFFFFu, s1, o);
        s2 += __shfl_xor_sync(0xFFFFFFFFu, s2, o);
        s3 += __shfl_xor_sync(0xFFFFFFFFu, s3, o);
        s4 += __shfl_xor_sync(0xFFFFFFFFu, s4, o);
    }
    if ((tid & 31) == 0) {
        int w = tid >> 5;
        red[w] = s1; red[8 + w] = s2; red[16 + w] = s3; red[24 + w] = s4;
    }
    __syncthreads();
    float t1 = 0.f, t2 = 0.f, t3 = 0.f, t4 = 0.f;
    #pragma unroll
    for (int i = 0; i < 8; i++) {
        t1 += red[i]; t2 += red[8 + i]; t3 += red[16 + i]; t4 += red[24 + i];
    }
    float mf = t1 * (1.0f / CC);
    float lf = (vf - mf) * rsqrtf(t2 * (1.0f / CC) - mf * mf + LN_EPS);
    float mb = t3 * (1.0f / CC);
    float lb = (vb - mb) * rsqrtf(t4 * (1.0f / CC) - mb * mb + LN_EPS);

    out[idx] = gelu_f(y[idx] + lf + lb);
}

// ---------------------------------------------------------------------------
// Host orchestration
// ---------------------------------------------------------------------------
static float* sym_addr(const void* sym) {
    void* p = 0;
    cudaGetSymbolAddress(&p, sym);
    return (float*)p;
}

extern "C" void kernel_launch(void* const* d_in, const int* in_sizes, int n_in,
                              void* d_out, int out_size) {
    const float* x        = (const float*)d_in[0];
    const float* Win_s    = (const float*)d_in[1];
    const float* bin_s    = (const float*)d_in[2];
    const float* att0     = (const float*)d_in[3];
    const float* Wout_s   = (const float*)d_in[4];
    const float* bout_s   = (const float*)d_in[5];
    const float* Wff_s    = (const float*)d_in[6];
    const float* bff_s    = (const float*)d_in[7];
    const float* Win_tf   = (const float*)d_in[8];
    const float* bin_tf   = (const float*)d_in[9];
    const float* Win_tb   = (const float*)d_in[10];
    const float* bin_tb   = (const float*)d_in[11];
    const float* Wout_tf  = (const float*)d_in[12];
    const float* bout_tf  = (const float*)d_in[13];
    const float* Wout_tb  = (const float*)d_in[14];
    const float* bout_tb  = (const float*)d_in[15];
    const float* Wff_t    = (const float*)d_in[16];
    const float* bff_t    = (const float*)d_in[17];
    float* out = (float*)d_out;

    float* big  = sym_addr(g_big);
    float* preA = sym_addr(g_preA);
    float* preB = sym_addr(g_preB);
    float* ybuf = sym_addr(g_y);
    float* atts = sym_addr(g_atts);
    float* attt = sym_addr(g_attt);

    float* qk   = big;   // [NTV,QKN]  alias — consumed before cat is written
    float* cat  = big;   // [NTV,CATN]
    float* zbuf = big;   // [NTV,CC]   alias — cat fully consumed before write

    const dim3 blk(256);
    const dim3 g_in(QKN / 128, NTV / 128);   // 3 x 800
    const dim3 g_out(CC / 128, NTV / 128);   // 2 x 800

    // ---- spatial block ----
    sgemm_kernel<1><<<g_in, blk>>>(x, Win_s, bin_s, qk, NTV, CC, QKN);
    spatial_att_kernel<<<NN * SS, blk>>>(qk, att0, atts);
    spatial_apply_kernel<<<NN * TT, blk>>>(atts, x, cat);
    sgemm_kernel<0><<<g_out, blk>>>(cat, Wout_s, bout_s, preA, NTV, CATN, CC);
    ln_add_gelu2_kernel<<<NTV, 256>>>(preA, x, ybuf);
    sgemm_kernel<0><<<g_out, blk>>>(ybuf, Wff_s, bff_s, preA, NTV, CC, CC);
    ln_add_gelu2_kernel<<<NTV, 256>>>(preA, x, ybuf);

    // ---- temporal forward ----
    sgemm_kernel<1><<<g_in, blk>>>(ybuf, Win_tf, bin_tf, qk, NTV, CC, QKN);
    temporal_att_kernel<<<NN * SS, blk>>>(qk, attt, 1);
    temporal_apply_kernel<<<NN * VV, blk>>>(attt, ybuf, cat);
    sgemm_kernel<0><<<g_out, blk>>>(cat, Wout_tf, bout_tf, preA, NTV, CATN, CC);

    // ---- temporal backward ----
    sgemm_kernel<1><<<g_in, blk>>>(ybuf, Win_tb, bin_tb, qk, NTV, CC, QKN);
    temporal_att_kernel<<<NN * SS, blk>>>(qk, attt, 0);
    temporal_apply_kernel<<<NN * VV, blk>>>(attt, ybuf, cat);
    sgemm_kernel<0><<<g_out, blk>>>(cat, Wout_tb, bout_tb, preB, NTV, CATN, CC);

    // ---- combine + final FF ----
    ln2_add_gelu3_kernel<<<NTV, 256>>>(preA, preB, ybuf, zbuf);
    sgemm_kernel<0><<<g_out, blk>>>(zbuf, Wff_t, bff_t, preA, NTV, CC, CC);
    ln_add_gelu2_kernel<<<NTV, 256>>>(preA, ybuf, out);
}

// round 6
// speedup vs baseline: 1.8967x; 1.4250x over previous
#include <cuda_runtime.h>
#include <cuda_bf16.h>
#include <math.h>
#include <stdint.h>

// Problem constants
#define NN   128
#define TT   32
#define VV   25
#define CC   256
#define ICC  64
#define SS   3
#define NTV  (NN*TT*VV)        // 102400 rows
#define QKN  (2*SS*ICC)        // 384
#define CATN (SS*CC)           // 768
#define LN_EPS 1e-5f

// ---------------------------------------------------------------------------
// Scratch (device globals; allocations are forbidden). ~634 MB total.
// ---------------------------------------------------------------------------
__device__ float g_big [NTV * CATN];       // 315 MB : qk / cat / z (aliased)
__device__ float g_preA[NTV * CC];         // 105 MB
__device__ float g_preB[NTV * CC];         // 105 MB
__device__ float g_y   [NTV * CC];         // 105 MB
__device__ float g_atts[NN * SS * VV * VV];
__device__ float g_attt[NN * SS * TT * TT];
// Transposed split-bf16 weights: per weight block [hi(N*K), lo(N*K)], K-major.
__device__ __align__(16) __nv_bfloat16 g_wt[2031616];   // ~4 MB

// Weight block offsets (elements)
#define O_WIN_S   0         // N=384,K=256  (98304 each)
#define O_WOUT_S  196608    // N=256,K=768  (196608 each)
#define O_WFF_S   589824    // N=256,K=256  (65536 each)
#define O_WIN_TF  720896
#define O_WIN_TB  917504
#define O_WOUT_TF 1114112
#define O_WOUT_TB 1507328
#define O_WFF_T   1900544

__device__ __forceinline__ float gelu_f(float x) {
    return 0.5f * x * (1.0f + erff(x * 0.70710678118654752f));
}

// ---------------------------------------------------------------------------
// HMMA helpers (baseline PTX, valid on sm_100 without 'a')
// ---------------------------------------------------------------------------
__device__ __forceinline__ uint32_t smem_u32(const void* p) {
    uint32_t a;
    asm("{ .reg .u64 t; cvta.to.shared.u64 t, %1; cvt.u32.u64 %0, t; }"
        : "=r"(a) : "l"(p));
    return a;
}
__device__ __forceinline__ void ldsm4(uint32_t* r, uint32_t addr) {
    asm volatile("ldmatrix.sync.aligned.m8n8.x4.shared.b16 {%0,%1,%2,%3}, [%4];"
        : "=r"(r[0]), "=r"(r[1]), "=r"(r[2]), "=r"(r[3]) : "r"(addr));
}
__device__ __forceinline__ void mma16816(float* c, const uint32_t* a,
                                         const uint32_t* b) {
    asm volatile(
        "mma.sync.aligned.m16n8k16.row.col.f32.bf16.bf16.f32 "
        "{%0,%1,%2,%3}, {%4,%5,%6,%7}, {%8,%9}, {%0,%1,%2,%3};"
        : "+f"(c[0]), "+f"(c[1]), "+f"(c[2]), "+f"(c[3])
        : "r"(a[0]), "r"(a[1]), "r"(a[2]), "r"(a[3]), "r"(b[0]), "r"(b[1]));
}

// ---------------------------------------------------------------------------
// Weight transpose + split-bf16 convert: W[K,N] -> Th[N,K], Tl[N,K] (bf16)
// ---------------------------------------------------------------------------
__global__ void wconv_kernel(const float* __restrict__ W,
                             __nv_bfloat16* __restrict__ Th,
                             __nv_bfloat16* __restrict__ Tl,
                             int K, int N) {
    int idx = blockIdx.x * 256 + threadIdx.x;   // idx = n*K + k
    if (idx >= K * N) return;
    int n = idx / K, k = idx - n * K;
    float w = W[(long)k * N + n];
    __nv_bfloat16 h = __float2bfloat16_rn(w);
    Th[idx] = h;
    Tl[idx] = __float2bfloat16_rn(w - __bfloat162float(h));
}

// ---------------------------------------------------------------------------
// Tensor-core GEMM via mma.sync:  C[M,Nc] = epi(A[M,K] @ W[K,Nc] + bias)
// A fp32 (split to bf16 hi/lo on the fly); W pre-split K-major [Nc,K].
// BM=BN=128, BK=32; 256 threads = 8 warps as 2(M) x 4(N); warp tile 64x32.
// 3-term split accumulation: hi*hi + hi*lo + lo*hi (fp32 accum in HMMA).
// SMEM stride 40 bf16 (80B) -> conflict-free ldmatrix.
// EPI: 0 = bias only, 1 = elu(v)+1
// ---------------------------------------------------------------------------
#define SMPITCH 40
template<int EPI>
__global__ void __launch_bounds__(256)
gemm_mma(const float* __restrict__ A,
         const __nv_bfloat16* __restrict__ Bh,
         const __nv_bfloat16* __restrict__ Bl,
         const float* __restrict__ bias,
         float* __restrict__ C,
         int M, int K, int Nc) {
    extern __shared__ char smc[];
    const uint32_t sb   = smem_u32(smc);
    const uint32_t smAh = sb;
    const uint32_t smAl = sb + 128 * SMPITCH * 2;
    const uint32_t smBh = sb + 2 * 128 * SMPITCH * 2;
    const uint32_t smBl = sb + 3 * 128 * SMPITCH * 2;

    const int tid  = threadIdx.x;
    const int lane = tid & 31;
    const int wid  = tid >> 5;
    const int warp_m = wid >> 2;      // 0..1 -> 64 rows
    const int warp_n = wid & 3;       // 0..3 -> 32 cols
    const int bm = blockIdx.y, bn = blockIdx.x;

    // Global load pointers (per-thread): row = tid>>1, half = tid&1 (16 elems)
    const int g_row  = tid >> 1;
    const int g_half = tid & 1;
    const float* Ap = A + (long)(bm * 128 + g_row) * K + g_half * 16;
    const __nv_bfloat16* Bhp = Bh + (long)(bn * 128 + g_row) * K + g_half * 16;
    const __nv_bfloat16* Blp = Bl + (long)(bn * 128 + g_row) * K + g_half * 16;

    // SMEM store addresses (bytes)
    const uint32_t stA = (uint32_t)(g_row * SMPITCH + g_half * 16) * 2;
    const uint32_t stB = stA;

    // ldmatrix base addresses
    uint32_t aAddrH[4], aAddrL[4], bAddrH[2], bAddrL[2];
    #pragma unroll
    for (int i = 0; i < 4; i++) {
        uint32_t off = ((uint32_t)((warp_m * 64 + i * 16 + (lane & 15)) * SMPITCH
                       + ((lane >> 4) & 1) * 8)) * 2;
        aAddrH[i] = smAh + off;
        aAddrL[i] = smAl + off;
    }
    #pragma unroll
    for (int p = 0; p < 2; p++) {
        uint32_t off = ((uint32_t)((warp_n * 32 + p * 16 + (lane & 7)
                       + ((lane >> 4) & 1) * 8) * SMPITCH
                       + ((lane >> 3) & 1) * 8)) * 2;
        bAddrH[p] = smBh + off;
        bAddrL[p] = smBl + off;
    }

    float c[4][4][4];
    #pragma unroll
    for (int i = 0; i < 4; i++)
        #pragma unroll
        for (int j = 0; j < 4; j++)
            #pragma unroll
            for (int q = 0; q < 4; q++) c[i][j][q] = 0.f;

    // Prologue: prefetch tile 0
    float4 ar[4];
    uint4 bhr[2], blr[2];
    #pragma unroll
    for (int j = 0; j < 4; j++) ar[j] = *(const float4*)(Ap + j * 4);
    #pragma unroll
    for (int j = 0; j < 2; j++) {
        bhr[j] = *(const uint4*)(Bhp + j * 8);
        blr[j] = *(const uint4*)(Blp + j * 8);
    }

    for (int kt = 0; kt < K; kt += 32) {
        // store staged regs -> smem (A converted to hi/lo)
        #pragma unroll
        for (int j = 0; j < 4; j++) {
            float4 v = ar[j];
            __nv_bfloat162 h01 = __float22bfloat162_rn(make_float2(v.x, v.y));
            __nv_bfloat162 h23 = __float22bfloat162_rn(make_float2(v.z, v.w));
            float2 f01 = __bfloat1622float2(h01);
            float2 f23 = __bfloat1622float2(h23);
            __nv_bfloat162 l01 = __float22bfloat162_rn(
                make_float2(v.x - f01.x, v.y - f01.y));
            __nv_bfloat162 l23 = __float22bfloat162_rn(
                make_float2(v.z - f23.x, v.w - f23.y));
            uint2 hv, lv;
            hv.x = *(uint32_t*)&h01;  hv.y = *(uint32_t*)&h23;
            lv.x = *(uint32_t*)&l01;  lv.y = *(uint32_t*)&l23;
            *(uint2*)(smc + (smAh - sb) + stA + j * 8) = hv;
            *(uint2*)(smc + (smAl - sb) + stA + j * 8) = lv;
        }
        #pragma unroll
        for (int j = 0; j < 2; j++) {
            *(uint4*)(smc + (smBh - sb) + stB + j * 16) = bhr[j];
            *(uint4*)(smc + (smBl - sb) + stB + j * 16) = blr[j];
        }
        __syncthreads();

        // prefetch next tile while mma runs
        if (kt + 32 < K) {
            #pragma unroll
            for (int j = 0; j < 4; j++)
                ar[j] = *(const float4*)(Ap + kt + 32 + j * 4);
            #pragma unroll
            for (int j = 0; j < 2; j++) {
                bhr[j] = *(const uint4*)(Bhp + kt + 32 + j * 8);
                blr[j] = *(const uint4*)(Blp + kt + 32 + j * 8);
            }
        }

        #pragma unroll
        for (int ks = 0; ks < 2; ks++) {
            uint32_t ah[4][4], al[4][4], bh[4][2], bl[4][2];
            #pragma unroll
            for (int i = 0; i < 4; i++) {
                ldsm4(ah[i], aAddrH[i] + ks * 32);
                ldsm4(al[i], aAddrL[i] + ks * 32);
            }
            #pragma unroll
            for (int p = 0; p < 2; p++) {
                uint32_t t[4];
                ldsm4(t, bAddrH[p] + ks * 32);
                bh[2 * p][0] = t[0];  bh[2 * p][1] = t[1];
                bh[2 * p + 1][0] = t[2];  bh[2 * p + 1][1] = t[3];
                ldsm4(t, bAddrL[p] + ks * 32);
                bl[2 * p][0] = t[0];  bl[2 * p][1] = t[1];
                bl[2 * p + 1][0] = t[2];  bl[2 * p + 1][1] = t[3];
            }
            #pragma unroll
            for (int i = 0; i < 4; i++)
                #pragma unroll
                for (int j = 0; j < 4; j++) {
                    mma16816(c[i][j], ah[i], bh[j]);
                    mma16816(c[i][j], ah[i], bl[j]);
                    mma16816(c[i][j], al[i], bh[j]);
                }
        }
        __syncthreads();
    }

    // Epilogue: fragment (r,c): c0,c1 -> (lane>>2, (lane&3)*2); c2,c3 -> +8 rows
    const int row_base = bm * 128 + warp_m * 64 + (lane >> 2);
    const int col_base = bn * 128 + warp_n * 32 + (lane & 3) * 2;
    #pragma unroll
    for (int i = 0; i < 4; i++) {
        #pragma unroll
        for (int j = 0; j < 4; j++) {
            const int col = col_base + j * 8;
            float2 bb = *(const float2*)(bias + col);
            const long r0 = row_base + i * 16;
            float2 o0, o1;
            o0.x = c[i][j][0] + bb.x;  o0.y = c[i][j][1] + bb.y;
            o1.x = c[i][j][2] + bb.x;  o1.y = c[i][j][3] + bb.y;
            if (EPI == 1) {
                o0.x = o0.x > 0.f ? o0.x + 1.f : __expf(o0.x);
                o0.y = o0.y > 0.f ? o0.y + 1.f : __expf(o0.y);
                o1.x = o1.x > 0.f ? o1.x + 1.f : __expf(o1.x);
                o1.y = o1.y > 0.f ? o1.y + 1.f : __expf(o1.y);
            }
            *(float2*)&C[r0 * Nc + col]       = o0;
            *(float2*)&C[(r0 + 8) * Nc + col] = o1;
        }
    }
}
#define SMEM_MMA (4 * 128 * SMPITCH * 2)   // 40960 bytes

// ---------------------------------------------------------------------------
// Spatial attention: att[n,s,v,u] = norm_u( sum_{t,ic} q k ) + att0[s,v,u]
// ---------------------------------------------------------------------------
__global__ void spatial_att_kernel(const float* __restrict__ qk,
                                   const float* __restrict__ att0,
                                   float* __restrict__ att) {
    const int n = blockIdx.x / SS;
    const int s = blockIdx.x % SS;
    const int tid = threadIdx.x;

    __shared__ float qs[VV][65];
    __shared__ float ks[VV][65];
    __shared__ float osh[VV * VV];
    __shared__ float rsum[VV];

    float acc[3] = {0.f, 0.f, 0.f};

    for (int t = 0; t < TT; t++) {
        for (int idx = tid; idx < VV * ICC; idx += 256) {
            int v  = idx >> 6;
            int ic = idx & 63;
            int base = ((n * TT + t) * VV + v) * QKN + ic * (2 * SS);
            qs[v][ic] = qk[base + s];
            ks[v][ic] = qk[base + s + SS];
        }
        __syncthreads();
        #pragma unroll
        for (int j = 0; j < 3; j++) {
            int o = tid + j * 256;
            if (o < VV * VV) {
                int v = o / VV, u = o % VV;
                float a = acc[j];
                #pragma unroll
                for (int ic = 0; ic < ICC; ic++) a += qs[v][ic] * ks[u][ic];
                acc[j] = a;
            }
        }
        __syncthreads();
    }
    #pragma unroll
    for (int j = 0; j < 3; j++) {
        int o = tid + j * 256;
        if (o < VV * VV) osh[o] = acc[j];
    }
    __syncthreads();
    if (tid < VV) {
        float sm = 0.f;
        #pragma unroll
        for (int u = 0; u < VV; u++) sm += osh[tid * VV + u];
        rsum[tid] = sm;
    }
    __syncthreads();
    #pragma unroll
    for (int j = 0; j < 3; j++) {
        int o = tid + j * 256;
        if (o < VV * VV) {
            int v = o / VV;
            att[(n * SS + s) * (VV * VV) + o] =
                osh[o] / rsum[v] + att0[s * (VV * VV) + o];
        }
    }
}

// ---------------------------------------------------------------------------
// Spatial apply: ycat[n,t,v, c*3+s] = sum_u att[n,s,v,u] * x[n,t,u,c]
// ---------------------------------------------------------------------------
__global__ void spatial_apply_kernel(const float* __restrict__ att,
                                     const float* __restrict__ x,
                                     float* __restrict__ ycat) {
    const int n = blockIdx.x / TT;
    const int t = blockIdx.x % TT;
    const int tid = threadIdx.x;

    __shared__ float xs[VV][CC];
    __shared__ float as[SS][VV][VV];

    for (int idx = tid; idx < VV * CC; idx += 256) {
        int u = idx >> 8, c = idx & 255;
        xs[u][c] = x[((n * TT + t) * VV + u) * CC + c];
    }
    for (int idx = tid; idx < SS * VV * VV; idx += 256)
        ((float*)as)[idx] = att[n * SS * VV * VV + idx];
    __syncthreads();

    const int c = tid;
    for (int v = 0; v < VV; v++) {
        float a0 = 0.f, a1 = 0.f, a2 = 0.f;
        #pragma unroll
        for (int u = 0; u < VV; u++) {
            float xv = xs[u][c];
            a0 += as[0][v][u] * xv;
            a1 += as[1][v][u] * xv;
            a2 += as[2][v][u] * xv;
        }
        int base = ((n * TT + t) * VV + v) * CATN + c * 3;
        ycat[base + 0] = a0;
        ycat[base + 1] = a1;
        ycat[base + 2] = a2;
    }
}

// ---------------------------------------------------------------------------
// Temporal attention: a[n,s,t,k] = norm_k( mask * sum_{v,ic} q k )
// ---------------------------------------------------------------------------
__global__ void temporal_att_kernel(const float* __restrict__ qk,
                                    float* __restrict__ att,
                                    int forward) {
    const int n = blockIdx.x / SS;
    const int s = blockIdx.x % SS;
    const int tid = threadIdx.x;

    __shared__ float qs[TT][65];
    __shared__ float ks[TT][65];
    __shared__ float osh[TT][TT + 1];
    __shared__ float rsum[TT];

    float acc[4] = {0.f, 0.f, 0.f, 0.f};

    for (int v = 0; v < VV; v++) {
        for (int idx = tid; idx < TT * ICC; idx += 256) {
            int t  = idx >> 6;
            int ic = idx & 63;
            int base = ((n * TT + t) * VV + v) * QKN + ic * (2 * SS);
            qs[t][ic] = qk[base + s];
            ks[t][ic] = qk[base + s + SS];
        }
        __syncthreads();
        #pragma unroll
        for (int j = 0; j < 4; j++) {
            int o = tid + j * 256;
            int t = o >> 5, k2 = o & 31;
            float a = acc[j];
            #pragma unroll
            for (int ic = 0; ic < ICC; ic++) a += qs[t][ic] * ks[k2][ic];
            acc[j] = a;
        }
        __syncthreads();
    }
    #pragma unroll
    for (int j = 0; j < 4; j++) {
        int o = tid + j * 256;
        int t = o >> 5, k2 = o & 31;
        bool keep = forward ? (k2 <= t) : (k2 >= t);
        osh[t][k2] = keep ? acc[j] : 0.f;
    }
    __syncthreads();
    if (tid < TT) {
        float sm = 0.f;
        #pragma unroll
        for (int k2 = 0; k2 < TT; k2++) sm += osh[tid][k2];
        rsum[tid] = sm;
    }
    __syncthreads();
    #pragma unroll
    for (int j = 0; j < 4; j++) {
        int o = tid + j * 256;
        int t = o >> 5, k2 = o & 31;
        att[(n * SS + s) * (TT * TT) + o] = osh[t][k2] / rsum[t];
    }
}

// ---------------------------------------------------------------------------
// Temporal apply: zcat[n,t,v, c*3+s] = sum_k a[n,s,t,k] * y[n,k,v,c]
// ---------------------------------------------------------------------------
__global__ void temporal_apply_kernel(const float* __restrict__ att,
                                      const float* __restrict__ y,
                                      float* __restrict__ zcat) {
    const int n = blockIdx.x / VV;
    const int v = blockIdx.x % VV;
    const int tid = threadIdx.x;

    __shared__ float ys[TT][CC];
    __shared__ float as[SS][TT][TT];

    for (int idx = tid; idx < TT * CC; idx += 256) {
        int k = idx >> 8, c = idx & 255;
        ys[k][c] = y[((n * TT + k) * VV + v) * CC + c];
    }
    for (int idx = tid; idx < SS * TT * TT; idx += 256)
        ((float*)as)[idx] = att[n * SS * TT * TT + idx];
    __syncthreads();

    const int c = tid;
    for (int t = 0; t < TT; t++) {
        float a0 = 0.f, a1 = 0.f, a2 = 0.f;
        #pragma unroll
        for (int k = 0; k < TT; k++) {
            float yv = ys[k][c];
            a0 += as[0][t][k] * yv;
            a1 += as[1][t][k] * yv;
            a2 += as[2][t][k] * yv;
        }
        int base = ((n * TT + t) * VV + v) * CATN + c * 3;
        zcat[base + 0] = a0;
        zcat[base + 1] = a1;
        zcat[base + 2] = a2;
    }
}

// ---------------------------------------------------------------------------
// Fused LayerNorm (+residual +GELU). One 256-thread block per row (C=256).
// ---------------------------------------------------------------------------
__global__ void ln_add_gelu2_kernel(const float* __restrict__ pre,
                                    const float* __restrict__ resid,
                                    float* __restrict__ out) {
    __shared__ float red[16];
    const int row = blockIdx.x;
    const int tid = threadIdx.x;
    const long idx = (long)row * CC + tid;

    float v = pre[idx];
    float s1 = v, s2 = v * v;
    #pragma unroll
    for (int o = 16; o > 0; o >>= 1) {
        s1 += __shfl_xor_sync(0xFFFFFFFFu, s1, o);
        s2 += __shfl_xor_sync(0xFFFFFFFFu, s2, o);
    }
    if ((tid & 31) == 0) { red[tid >> 5] = s1; red[8 + (tid >> 5)] = s2; }
    __syncthreads();
    float t1 = 0.f, t2 = 0.f;
    #pragma unroll
    for (int i = 0; i < 8; i++) { t1 += red[i]; t2 += red[8 + i]; }
    float mean = t1 * (1.0f / CC);
    float var  = t2 * (1.0f / CC) - mean * mean;
    float ln   = (v - mean) * rsqrtf(var + LN_EPS);

    out[idx] = gelu_f(resid[idx] + ln);
}

__global__ void ln2_add_gelu3_kernel(const float* __restrict__ preF,
                                     const float* __restrict__ preB,
                                     const float* __restrict__ y,
                                     float* __restrict__ out) {
    __shared__ float red[32];
    const int row = blockIdx.x;
    const int tid = threadIdx.x;
    const long idx = (long)row * CC + tid;

    float vf = preF[idx];
    float vb = preB[idx];
    float s1 = vf, s2 = vf * vf, s3 = vb, s4 = vb * vb;
    #pragma unroll
    for (int o = 16; o > 0; o >>= 1) {
        s1 += __shfl_xor_sync(0xFFFFFFFFu, s1, o);
        s2 += __shfl_xor_sync(0xFFFFFFFFu, s2, o);
        s3 += __shfl_xor_sync(0xFFFFFFFFu, s3, o);
        s4 += __shfl_xor_sync(0xFFFFFFFFu, s4, o);
    }
    if ((tid & 31) == 0) {
        int w = tid >> 5;
        red[w] = s1; red[8 + w] = s2; red[16 + w] = s3; red[24 + w] = s4;
    }
    __syncthreads();
    float t1 = 0.f, t2 = 0.f, t3 = 0.f, t4 = 0.f;
    #pragma unroll
    for (int i = 0; i < 8; i++) {
        t1 += red[i]; t2 += red[8 + i]; t3 += red[16 + i]; t4 += red[24 + i];
    }
    float mf = t1 * (1.0f / CC);
    float lf = (vf - mf) * rsqrtf(t2 * (1.0f / CC) - mf * mf + LN_EPS);
    float mb = t3 * (1.0f / CC);
    float lb = (vb - mb) * rsqrtf(t4 * (1.0f / CC) - mb * mb + LN_EPS);

    out[idx] = gelu_f(y[idx] + lf + lb);
}

// ---------------------------------------------------------------------------
// Host orchestration
// ---------------------------------------------------------------------------
static float* sym_addr(const void* sym) {
    void* p = 0;
    cudaGetSymbolAddress(&p, sym);
    return (float*)p;
}

extern "C" void kernel_launch(void* const* d_in, const int* in_sizes, int n_in,
                              void* d_out, int out_size) {
    const float* x        = (const float*)d_in[0];
    const float* Win_s    = (const float*)d_in[1];
    const float* bin_s    = (const float*)d_in[2];
    const float* att0     = (const float*)d_in[3];
    const float* Wout_s   = (const float*)d_in[4];
    const float* bout_s   = (const float*)d_in[5];
    const float* Wff_s    = (const float*)d_in[6];
    const float* bff_s    = (const float*)d_in[7];
    const float* Win_tf   = (const float*)d_in[8];
    const float* bin_tf   = (const float*)d_in[9];
    const float* Win_tb   = (const float*)d_in[10];
    const float* bin_tb   = (const float*)d_in[11];
    const float* Wout_tf  = (const float*)d_in[12];
    const float* bout_tf  = (const float*)d_in[13];
    const float* Wout_tb  = (const float*)d_in[14];
    const float* bout_tb  = (const float*)d_in[15];
    const float* Wff_t    = (const float*)d_in[16];
    const float* bff_t    = (const float*)d_in[17];
    float* out = (float*)d_out;

    float* big  = sym_addr(g_big);
    float* preA = sym_addr(g_preA);
    float* preB = sym_addr(g_preB);
    float* ybuf = sym_addr(g_y);
    float* atts = sym_addr(g_atts);
    float* attt = sym_addr(g_attt);
    __nv_bfloat16* wt = (__nv_bfloat16*)sym_addr(g_wt);

    float* qk   = big;   // [NTV,QKN]  alias — consumed before cat is written
    float* cat  = big;   // [NTV,CATN]
    float* zbuf = big;   // [NTV,CC]   alias — cat fully consumed before write

    // ---- weight prep: transpose + split-bf16 ----
    #define WCONV(W, OFF, Kk, Nn) \
        wconv_kernel<<<((Kk)*(Nn) + 255) / 256, 256>>>(W, wt + (OFF), \
            wt + (OFF) + (long)(Kk)*(Nn), Kk, Nn)
    WCONV(Win_s,   O_WIN_S,   CC,   QKN);
    WCONV(Wout_s,  O_WOUT_S,  CATN, CC);
    WCONV(Wff_s,   O_WFF_S,   CC,   CC);
    WCONV(Win_tf,  O_WIN_TF,  CC,   QKN);
    WCONV(Win_tb,  O_WIN_TB,  CC,   QKN);
    WCONV(Wout_tf, O_WOUT_TF, CATN, CC);
    WCONV(Wout_tb, O_WOUT_TB, CATN, CC);
    WCONV(Wff_t,   O_WFF_T,   CC,   CC);
    #undef WCONV

    const dim3 blk256(256);
    const dim3 g_in(QKN / 128, NTV / 128);   // 3 x 800
    const dim3 g_out(CC / 128, NTV / 128);   // 2 x 800

    #define GEMM(EPI, A, OFF, NK, BIAS, Cp, Kk, Nn, GRID) \
        gemm_mma<EPI><<<GRID, blk256, SMEM_MMA>>>(A, wt + (OFF), \
            wt + (OFF) + (NK), BIAS, Cp, NTV, Kk, Nn)

    // ---- spatial block ----
    GEMM(1, x, O_WIN_S, 98304, bin_s, qk, CC, QKN, g_in);
    spatial_att_kernel<<<NN * SS, 256>>>(qk, att0, atts);
    spatial_apply_kernel<<<NN * TT, 256>>>(atts, x, cat);
    GEMM(0, cat, O_WOUT_S, 196608, bout_s, preA, CATN, CC, g_out);
    ln_add_gelu2_kernel<<<NTV, 256>>>(preA, x, ybuf);
    GEMM(0, ybuf, O_WFF_S, 65536, bff_s, preA, CC, CC, g_out);
    ln_add_gelu2_kernel<<<NTV, 256>>>(preA, x, ybuf);

    // ---- temporal forward ----
    GEMM(1, ybuf, O_WIN_TF, 98304, bin_tf, qk, CC, QKN, g_in);
    temporal_att_kernel<<<NN * SS, 256>>>(qk, attt, 1);
    temporal_apply_kernel<<<NN * VV, 256>>>(attt, ybuf, cat);
    GEMM(0, cat, O_WOUT_TF, 196608, bout_tf, preA, CATN, CC, g_out);

    // ---- temporal backward ----
    GEMM(1, ybuf, O_WIN_TB, 98304, bin_tb, qk, CC, QKN, g_in);
    temporal_att_kernel<<<NN * SS, 256>>>(qk, attt, 0);
    temporal_apply_kernel<<<NN * VV, 256>>>(attt, ybuf, cat);
    GEMM(0, cat, O_WOUT_TB, 196608, bout_tb, preB, CATN, CC, g_out);

    // ---- combine + final FF ----
    ln2_add_gelu3_kernel<<<NTV, 256>>>(preA, preB, ybuf, zbuf);
    GEMM(0, zbuf, O_WFF_T, 65536, bff_t, preA, CC, CC, g_out);
    ln_add_gelu2_kernel<<<NTV, 256>>>(preA, ybuf, out);
    #undef GEMM
}